// round 15
// baseline (speedup 1.0000x reference)
#include <cuda_runtime.h>
#include <math_constants.h>

// Problem constants (fixed shapes from setup_inputs)
#define BB   8      // batch
#define NPTS 256    // N = 4096/16
#define BETA 192    // 0.75*N
#define KN   768    // 3*N oversampled points
#define CO   128    // out channels
#define HO   256
#define WO   256
#define CF   64     // res2 channels
#define HF   512
#define WF   512
#define CFEAT (CO + CF)   // 192
#define RPTS 8            // points per render block

__device__ float g_unc[BB * KN];
__device__ __align__(16) float g_featC[BB * KN * CO];   // cached coarse features
__device__ int   g_idx[BB * BETA];                      // selected oversample idx

#define PACK_F32X2(out, lo, hi) \
    asm("mov.b64 %0, {%1, %2};" : "=l"(out) : "f"(lo), "f"(hi))
#define FFMA2(acc, a, b) \
    asm("fma.rn.f32x2 %0, %1, %2, %0;" : "+l"(acc) : "l"(a), "l"(b))

// merge running top2 (m1>=m2) with single value v
__device__ __forceinline__ void merge1(float &m1, float &m2, float v) {
    float n1 = fmaxf(m1, v);
    m2 = fmaxf(fminf(m1, v), m2);
    m1 = n1;
}
// merge running top2 with another pair (o1>=o2)
__device__ __forceinline__ void merge2(float &m1, float &m2, float o1, float o2) {
    float n1 = fmaxf(m1, o1);
    float n2 = fmaxf(fminf(m1, o1), fmaxf(m2, o2));
    m1 = n1; m2 = n2;
}

// ---------------------------------------------------------------------------
// Kernel 1: per-point uncertainty + coarse-feature cache.
// 2 warps per point (one per bilinear row); block = 4 points (256 thr).
// ---------------------------------------------------------------------------
__global__ void uncert_kernel(const float* __restrict__ outm,
                              const float* __restrict__ rand_over) {
    __shared__ float part[4][2];
    __shared__ float rv[4][2][CO];    // per-point, per-row channel blends (4 KB)
    int tid = threadIdx.x;
    int wrp = tid >> 5;
    int lane = tid & 31;
    int ptl = wrp >> 1;          // local point 0..3
    int r   = wrp & 1;           // bilinear row 0/1
    int idx = blockIdx.x * 4 + ptl;   // global b*KN + p
    int b = idx / KN;

    float px = rand_over[idx * 2 + 0];
    float py = rand_over[idx * 2 + 1];
    float gx = px * (float)WO - 0.5f;
    float gy = py * (float)HO - 0.5f;
    float x0f = floorf(gx), y0f = floorf(gy);
    float wx = gx - x0f, wy = gy - y0f;
    int x0 = (int)x0f, y0 = (int)y0f;

    const float* base = outm + (long long)b * CO * HO * WO;
    bool xv0 = (x0 >= 0) && (x0 < WO);
    bool xv1 = (x0 + 1 >= 0) && (x0 + 1 < WO);
    int xc0 = min(max(x0, 0), WO - 1);
    int xc1 = min(max(x0 + 1, 0), WO - 1);

    int y = y0 + r;
    bool yv = (y >= 0) && (y < HO);
    int yc = min(max(y, 0), HO - 1);
    const float* rp = base + yc * WO;
    float wyr = r ? wy : (1.f - wy);

    // 8 scalar loads, batched for MLP
    float v0[4], v1[4];
#pragma unroll
    for (int cc = 0; cc < 4; cc++) {
        long long co = (long long)(lane + cc * 32) * (HO * WO);
        v0[cc] = __ldg(rp + co + xc0);
        v1[cc] = __ldg(rp + co + xc1);
    }

    // per-channel x-blend (cached for render's coarse gather)
    float m0 = (yv && xv0) ? 1.f : 0.f;
    float m1 = (yv && xv1) ? 1.f : 0.f;
#pragma unroll
    for (int cc = 0; cc < 4; cc++) {
        rv[ptl][r][lane + cc * 32] =
            wyr * ((1.f - wx) * m0 * v0[cc] + wx * m1 * v1[cc]);
    }

    float a1 = -CUDART_INF_F, a2 = -CUDART_INF_F;   // corner x0
    float b1 = -CUDART_INF_F, b2 = -CUDART_INF_F;   // corner x0+1
#pragma unroll
    for (int cc = 0; cc < 4; cc++) {
        merge1(a1, a2, v0[cc]);
        merge1(b1, b2, v1[cc]);
    }
#pragma unroll
    for (int off = 16; off; off >>= 1) {
        merge2(a1, a2, __shfl_xor_sync(0xFFFFFFFFu, a1, off),
                       __shfl_xor_sync(0xFFFFFFFFu, a2, off));
        merge2(b1, b2, __shfl_xor_sync(0xFFFFFFFFu, b1, off),
                       __shfl_xor_sync(0xFFFFFFFFu, b2, off));
    }
    float e0 = (yv && xv0) ? (a2 - a1) : 0.f;   // -(top1 - top2), zero padded
    float e1 = (yv && xv1) ? (b2 - b1) : 0.f;
    if (lane == 0)
        part[ptl][r] = wyr * ((1.f - wx) * e0 + wx * e1);
    __syncthreads();

    if (r == 0 && lane == 0)
        g_unc[idx] = part[ptl][0] + part[ptl][1];

    // write cached coarse features: 4 pts x 128 ch, 2 entries per thread
#pragma unroll
    for (int it = 0; it < 2; it++) {
        int s = tid + it * 256;
        int pt = s >> 7;
        int c  = s & 127;
        g_featC[(long long)(blockIdx.x * 4 + pt) * CO + c] =
            rv[pt][0][c] + rv[pt][1][c];
    }
}

// ---------------------------------------------------------------------------
// Kernel 2: exact top-192 per batch; 4-keys-per-thread bitonic sort.
// 256 threads; key at global position g = t*4+i. j=1,2 in-register;
// j=4..64 via shfl (partner lane t^(j/4)); j=128,256,512 via smem.
// ---------------------------------------------------------------------------
__global__ void topk_kernel(const float* __restrict__ rand_over,
                            const float* __restrict__ rand_cov,
                            float* __restrict__ points) {
    int b = blockIdx.x;
    int t = threadIdx.x;
    __shared__ unsigned long long sk[1024];

    unsigned long long key[4];
#pragma unroll
    for (int i = 0; i < 4; i++) {
        int g = t * 4 + i;
        unsigned long long kk = 0ull;   // pad: sorts last
        if (g < KN) {
            float u = g_unc[b * KN + g];
            unsigned ub = __float_as_uint(u);
            ub = (ub & 0x80000000u) ? ~ub : (ub | 0x80000000u);  // total order
            kk = ((unsigned long long)ub << 32) |
                 (unsigned long long)(0xFFFFFFFFu - (unsigned)g);
        }
        key[i] = kk;
    }

    // compare-exchange: position g vs g^j; overall descending sort
    // d = (desc == iLower); keep max if d else min
#define CMP_LOCAL(i, j, k_) {                                              \
        int ii = (i), jj = (i) ^ (j);                                      \
        int g = t * 4 + ii;                                                \
        bool desc = ((g & (k_)) == 0);                                     \
        unsigned long long A = key[ii], Bv = key[jj];                      \
        unsigned long long mx = (A > Bv) ? A : Bv;                         \
        unsigned long long mn = (A > Bv) ? Bv : A;                         \
        key[ii] = desc ? mx : mn;                                          \
        key[jj] = desc ? mn : mx;                                          \
    }

    for (int k = 2; k <= 1024; k <<= 1) {
        for (int j = k >> 1; j; j >>= 1) {
            if (j >= 128) {
                // smem stage: partner thread t ^ (j/4)
                __syncthreads();
#pragma unroll
                for (int i = 0; i < 4; i++) sk[t * 4 + i] = key[i];
                __syncthreads();
                int pt = t ^ (j >> 2);
#pragma unroll
                for (int i = 0; i < 4; i++) {
                    unsigned long long other = sk[pt * 4 + i];
                    int g = t * 4 + i;
                    bool iLower = ((g & j) == 0);
                    bool desc   = ((g & k) == 0);
                    unsigned long long mx = (key[i] > other) ? key[i] : other;
                    unsigned long long mn = (key[i] > other) ? other : key[i];
                    key[i] = (desc == iLower) ? mx : mn;
                }
            } else if (j >= 4) {
                // shfl stage: partner lane t ^ (j/4), same i
                int lj = j >> 2;
#pragma unroll
                for (int i = 0; i < 4; i++) {
                    unsigned long long other = __shfl_xor_sync(0xFFFFFFFFu, key[i], lj);
                    int g = t * 4 + i;
                    bool iLower = ((g & j) == 0);
                    bool desc   = ((g & k) == 0);
                    unsigned long long mx = (key[i] > other) ? key[i] : other;
                    unsigned long long mn = (key[i] > other) ? other : key[i];
                    key[i] = (desc == iLower) ? mx : mn;
                }
            } else if (j == 2) {
                CMP_LOCAL(0, 2, k);
                CMP_LOCAL(1, 2, k);
            } else {  // j == 1
                CMP_LOCAL(0, 1, k);
                CMP_LOCAL(2, 1, k);
            }
        }
    }
#undef CMP_LOCAL

    // threads 0..47 hold sorted positions 0..191 (top-192, exact order)
    if (t < BETA / 4) {
#pragma unroll
        for (int i = 0; i < 4; i++) {
            int n = t * 4 + i;
            unsigned idx = 0xFFFFFFFFu - (unsigned)(key[i] & 0xFFFFFFFFull);
            g_idx[b * BETA + n] = (int)idx;
            points[(b * NPTS + n) * 2 + 0] = rand_over[(b * KN + idx) * 2 + 0];
            points[(b * NPTS + n) * 2 + 1] = rand_over[(b * KN + idx) * 2 + 1];
        }
    } else if (t >= 48 && t < 48 + (NPTS - BETA)) {
        int i = t - 48;
        int n = BETA + i;
        points[(b * NPTS + n) * 2 + 0] = rand_cov[(b * (NPTS - BETA) + i) * 2 + 0];
        points[(b * NPTS + n) * 2 + 1] = rand_cov[(b * (NPTS - BETA) + i) * 2 + 1];
    }
}

// ---------------------------------------------------------------------------
// Kernel 3 (fused render): gather 8 points x 192 ch into fs (coarse features
// of importance points come from the g_featC cache), then GEMM with
// smem-staged weight. grid = 256 blocks, 512 threads.
// ---------------------------------------------------------------------------
__device__ __forceinline__ float bilerp_sample(const float* __restrict__ base,
                                               int H, int W, float px, float py) {
    float gx = px * (float)W - 0.5f;
    float gy = py * (float)H - 0.5f;
    float x0f = floorf(gx), y0f = floorf(gy);
    float wx = gx - x0f, wy = gy - y0f;
    int x0 = (int)x0f, y0 = (int)y0f;
    bool xv0 = (x0 >= 0) && (x0 < W);
    bool xv1 = (x0 + 1 >= 0) && (x0 + 1 < W);
    bool yv0 = (y0 >= 0) && (y0 < H);
    bool yv1 = (y0 + 1 >= 0) && (y0 + 1 < H);
    int xc0 = min(max(x0, 0), W - 1);
    int xc1 = min(max(x0 + 1, 0), W - 1);
    int yc0 = min(max(y0, 0), H - 1);
    int yc1 = min(max(y0 + 1, 0), H - 1);

    const float* r0 = base + yc0 * W;
    const float* r1 = base + yc1 * W;
    float v00 = __ldg(r0 + xc0);
    float v01 = __ldg(r0 + xc1);
    float v10 = __ldg(r1 + xc0);
    float v11 = __ldg(r1 + xc1);
    v00 = (yv0 && xv0) ? v00 : 0.f;
    v01 = (yv0 && xv1) ? v01 : 0.f;
    v10 = (yv1 && xv0) ? v10 : 0.f;
    v11 = (yv1 && xv1) ? v11 : 0.f;
    return v00 * (1.f - wx) * (1.f - wy) + v01 * wx * (1.f - wy)
         + v10 * (1.f - wx) * wy + v11 * wx * wy;
}

__global__ __launch_bounds__(512) void render_kernel(
        const float* __restrict__ outm,
        const float* __restrict__ res2,
        const float* __restrict__ weight,
        const float* __restrict__ bias,
        const float* __restrict__ points,
        float* __restrict__ rend) {
    __shared__ float ws[CO][33];                    // one 32-k chunk, 16.9 KB
    __shared__ __align__(8) float fs[CFEAT][RPTS];  // 6 KB

    int blk = blockIdx.x;
    int b  = blk / (NPTS / RPTS);
    int n0 = (blk % (NPTS / RPTS)) * RPTS;
    int t = threadIdx.x;

    // ---- phase 1: gather 8*192 = 1536 samples, 3 per thread
#pragma unroll
    for (int it = 0; it < 3; it++) {
        int s = t + it * 512;
        int p = s / CFEAT;
        int k = s - p * CFEAT;
        int n = n0 + p;
        float v;
        if (k < CO) {
            if (n < BETA) {
                // importance point: cached bilinear coarse feature
                int gi = g_idx[b * BETA + n];
                v = __ldg(g_featC + (long long)(b * KN + gi) * CO + k);
            } else {
                float px = points[(b * NPTS + n) * 2 + 0];
                float py = points[(b * NPTS + n) * 2 + 1];
                v = bilerp_sample(outm + ((long long)(b * CO + k)) * (HO * WO),
                                  HO, WO, px, py);
            }
        } else {
            float px = points[(b * NPTS + n) * 2 + 0];
            float py = points[(b * NPTS + n) * 2 + 1];
            v = bilerp_sample(res2 + ((long long)(b * CF + (k - CO))) * (HF * WF),
                              HF, WF, px, py);
        }
        fs[k][p] = v;
    }

    // ---- phase 2: GEMM with k-chunked smem weight
    int o = t & 127;          // out channel
    int g = t >> 7;           // n-pair: (2g, 2g+1); warp-uniform
    unsigned long long acc = 0ull;

#pragma unroll
    for (int kc = 0; kc < CFEAT / 32; kc++) {
        __syncthreads();
        // stage ws[o][0..31] = weight[o][kc*32 .. +31]; coalesced float4 loads
#pragma unroll
        for (int j = t; j < CO * 8; j += 512) {
            int row = j >> 3, part = j & 7;
            float4 w4 = __ldg(reinterpret_cast<const float4*>(
                weight + row * CFEAT + kc * 32 + part * 4));
            ws[row][part * 4 + 0] = w4.x;
            ws[row][part * 4 + 1] = w4.y;
            ws[row][part * 4 + 2] = w4.z;
            ws[row][part * 4 + 3] = w4.w;
        }
        __syncthreads();

#pragma unroll
        for (int j = 0; j < 32; j++) {
            int k = kc * 32 + j;
            float wv = ws[o][j];                     // conflict-free (pad 33)
            unsigned long long wp;
            PACK_F32X2(wp, wv, wv);
            unsigned long long fpair =
                *reinterpret_cast<const unsigned long long*>(&fs[k][2 * g]);  // broadcast
            FFMA2(acc, wp, fpair);
        }
    }

    float bv = bias[o];
    float2 outv;
    outv.x = __uint_as_float((unsigned)(acc & 0xFFFFFFFFull)) + bv;
    outv.y = __uint_as_float((unsigned)(acc >> 32)) + bv;
    *reinterpret_cast<float2*>(rend + ((long long)b * CO + o) * NPTS + n0 + 2 * g) = outv;
}

// ---------------------------------------------------------------------------
// Launch
// ---------------------------------------------------------------------------
extern "C" void kernel_launch(void* const* d_in, const int* in_sizes, int n_in,
                              void* d_out, int out_size) {
    // metadata order: x, res2, out, rand_over, rand_cov, weight, bias
    const float* res2      = (const float*)d_in[1];
    const float* outm      = (const float*)d_in[2];
    const float* rand_over = (const float*)d_in[3];
    const float* rand_cov  = (const float*)d_in[4];
    const float* weight    = (const float*)d_in[5];
    const float* bias      = (const float*)d_in[6];

    float* rend   = (float*)d_out;                       // [B,128,256]
    float* points = (float*)d_out + BB * CO * NPTS;      // [B,256,2]

    // 2 warps per point (row-split), 4 points per 256-thread block
    uncert_kernel<<<(BB * KN) / 4, 256>>>(outm, rand_over);
    topk_kernel<<<BB, 256>>>(rand_over, rand_cov, points);
    render_kernel<<<BB * (NPTS / RPTS), 512>>>(outm, res2, weight, bias, points, rend);
}